// round 1
// baseline (speedup 1.0000x reference)
#include <cuda_runtime.h>
#include <math.h>

// ConfidenceCalibration: reference's bin_weights = softmax(...) sums to 1,
// so final = clip(base * scale, 0, 1) with base = sigmoid(mean(x, -1)) and
// scale = bin_scaling[bucketize(base)]. The two GEMMs / LN / GELU / softmax
// are multiplied away. Kernel is pure HBM-bound: read 128 MB of x once.
//
// Inputs (metadata order): x[B,D], w1, b1, ln_g, ln_b, w2, b2, bin_scaling[NB]
// Output: float[B]

__global__ void confcal_kernel(const float* __restrict__ x,
                               const float* __restrict__ bin_scaling,
                               float* __restrict__ out,
                               int B, int D, int NB) {
    const int gwarp = (blockIdx.x * blockDim.x + threadIdx.x) >> 5;
    const int lane  = threadIdx.x & 31;
    if (gwarp >= B) return;

    const float* rowp = x + (size_t)gwarp * (size_t)D;
    const int nvec = D >> 2;             // float4 count
    const float4* row4 = reinterpret_cast<const float4*>(rowp);

    float s = 0.0f;
    // Coalesced: 32 lanes * 16B = 512B contiguous per iteration; D=1024 -> 8 iters.
    #pragma unroll 4
    for (int i = lane; i < nvec; i += 32) {
        float4 v = row4[i];
        s += (v.x + v.y) + (v.z + v.w);
    }
    // Scalar tail for D % 4 != 0 (not hit for D=1024).
    for (int i = (nvec << 2) + lane; i < D; i += 32) s += rowp[i];

    // Warp reduction
    #pragma unroll
    for (int o = 16; o; o >>= 1) s += __shfl_xor_sync(0xffffffffu, s, o);

    if (lane == 0) {
        float mean = s / (float)D;
        float base = 1.0f / (1.0f + expf(-mean));   // sigmoid

        // bucketize: idx = searchsorted(linspace(0,1,NB+1), base, 'right') - 1
        //          = (count of boundaries <= base) - 1
        int idx = -1;
        for (int i = 0; i <= NB; i++) {
            float bnd = (float)i / (float)NB;
            if (bnd <= base) idx = i; else break;
        }
        // idx currently = largest i with boundary[i] <= base; searchsorted-1 semantics.
        float scale = (idx >= 0 && idx < NB) ? bin_scaling[idx] : 0.0f;
        float cal = base * scale;
        out[gwarp] = fminf(fmaxf(cal, 0.0f), 1.0f);
    }
}

extern "C" void kernel_launch(void* const* d_in, const int* in_sizes, int n_in,
                              void* d_out, int out_size) {
    const float* x            = (const float*)d_in[0];
    const float* bin_scaling  = (const float*)d_in[7];
    float* out = (float*)d_out;

    const int B  = out_size;                 // 32768
    const int D  = in_sizes[0] / B;          // 1024
    const int NB = in_sizes[7];              // 15

    const int threads = 256;                 // 8 warps -> 8 rows per block
    const int rows_per_block = threads / 32;
    const int blocks = (B + rows_per_block - 1) / rows_per_block;

    confcal_kernel<<<blocks, threads>>>(x, bin_scaling, out, B, D, NB);
}

// round 3
// speedup vs baseline: 1.0574x; 1.0574x over previous
#include <cuda_runtime.h>
#include <math.h>

// ConfidenceCalibration: softmax over bins sums to 1, so
// final = clip(sigmoid(mean(x,-1)) * bin_scaling[bucketize(...)], 0, 1).
// Pure HBM-streaming row reduction: 128 MB read once.
//
// R1 -> R2 change: D=1024 specialization with all 8 LDG.128 per lane issued
// back-to-back (front-batched MLP=8) via __ldcs (streaming, evict-first),
// then a pairwise tree sum. Raises MLP_eff 4->8 to push DRAM% 70 -> 80+.

__device__ __forceinline__ float warp_reduce_sum(float s) {
    #pragma unroll
    for (int o = 16; o; o >>= 1) s += __shfl_xor_sync(0xffffffffu, s, o);
    return s;
}

__device__ __forceinline__ void finalize(float s, int D, int NB,
                                         const float* __restrict__ bin_scaling,
                                         float* __restrict__ out, int row) {
    float mean = s / (float)D;
    float base = 1.0f / (1.0f + expf(-mean));
    // searchsorted(linspace(0,1,NB+1), base, 'right') - 1
    int idx = -1;
    for (int i = 0; i <= NB; i++) {
        float bnd = (float)i / (float)NB;
        if (bnd <= base) idx = i; else break;
    }
    float scale = (idx >= 0 && idx < NB) ? bin_scaling[idx] : 0.0f;
    out[row] = fminf(fmaxf(base * scale, 0.0f), 1.0f);
}

// Specialized: D == 1024 (8 x float4 per lane, fully unrolled, front-batched)
__global__ void __launch_bounds__(256) confcal_kernel_1024(
        const float* __restrict__ x,
        const float* __restrict__ bin_scaling,
        float* __restrict__ out,
        int B, int NB) {
    const int gwarp = (blockIdx.x * blockDim.x + threadIdx.x) >> 5;
    const int lane  = threadIdx.x & 31;
    if (gwarp >= B) return;

    const float4* row4 = reinterpret_cast<const float4*>(x + (size_t)gwarp * 1024u) + lane;

    // 8 independent streaming loads, all in flight before any arithmetic.
    float4 v0 = __ldcs(row4 + 0 * 32);
    float4 v1 = __ldcs(row4 + 1 * 32);
    float4 v2 = __ldcs(row4 + 2 * 32);
    float4 v3 = __ldcs(row4 + 3 * 32);
    float4 v4 = __ldcs(row4 + 4 * 32);
    float4 v5 = __ldcs(row4 + 5 * 32);
    float4 v6 = __ldcs(row4 + 6 * 32);
    float4 v7 = __ldcs(row4 + 7 * 32);

    // Pairwise tree sum (shorter dep chains than serial accumulate).
    float a0 = (v0.x + v0.y) + (v0.z + v0.w);
    float a1 = (v1.x + v1.y) + (v1.z + v1.w);
    float a2 = (v2.x + v2.y) + (v2.z + v2.w);
    float a3 = (v3.x + v3.y) + (v3.z + v3.w);
    float a4 = (v4.x + v4.y) + (v4.z + v4.w);
    float a5 = (v5.x + v5.y) + (v5.z + v5.w);
    float a6 = (v6.x + v6.y) + (v6.z + v6.w);
    float a7 = (v7.x + v7.y) + (v7.z + v7.w);
    float s = ((a0 + a1) + (a2 + a3)) + ((a4 + a5) + (a6 + a7));

    s = warp_reduce_sum(s);
    if (lane == 0) finalize(s, 1024, NB, bin_scaling, out, gwarp);
}

// Generic fallback for other D
__global__ void confcal_kernel_gen(const float* __restrict__ x,
                                   const float* __restrict__ bin_scaling,
                                   float* __restrict__ out,
                                   int B, int D, int NB) {
    const int gwarp = (blockIdx.x * blockDim.x + threadIdx.x) >> 5;
    const int lane  = threadIdx.x & 31;
    if (gwarp >= B) return;

    const float* rowp = x + (size_t)gwarp * (size_t)D;
    const int nvec = D >> 2;
    const float4* row4 = reinterpret_cast<const float4*>(rowp);

    float s = 0.0f;
    #pragma unroll 8
    for (int i = lane; i < nvec; i += 32) {
        float4 v = __ldcs(row4 + i);
        s += (v.x + v.y) + (v.z + v.w);
    }
    for (int i = (nvec << 2) + lane; i < D; i += 32) s += rowp[i];

    s = warp_reduce_sum(s);
    if (lane == 0) finalize(s, D, NB, bin_scaling, out, gwarp);
}

extern "C" void kernel_launch(void* const* d_in, const int* in_sizes, int n_in,
                              void* d_out, int out_size) {
    const float* x           = (const float*)d_in[0];
    const float* bin_scaling = (const float*)d_in[7];
    float* out = (float*)d_out;

    const int B  = out_size;            // 32768
    const int D  = in_sizes[0] / B;     // 1024
    const int NB = in_sizes[7];         // 15

    const int threads = 256;            // 8 warps = 8 rows per block
    const int rows_per_block = threads / 32;
    const int blocks = (B + rows_per_block - 1) / rows_per_block;

    if (D == 1024) {
        confcal_kernel_1024<<<blocks, threads>>>(x, bin_scaling, out, B, NB);
    } else {
        confcal_kernel_gen<<<blocks, threads>>>(x, bin_scaling, out, B, D, NB);
    }
}